// round 6
// baseline (speedup 1.0000x reference)
#include <cuda_runtime.h>
#include <math.h>

// Problem constants
#define BB    4
#define SEQ   1024
#define DIM   1024
#define NH    16
#define HDIM  64
#define CONDD 256
#define ADA_CH 9
#define ADA_N  (ADA_CH * DIM)   // 9216 (only the 9 used chunks of 12)

// ---------------------------------------------------------------------------
// Scratch (static device globals; no allocation allowed)
// ---------------------------------------------------------------------------
__device__ float g_ada   [(size_t)BB * SEQ * ADA_N];        // 151 MB
__device__ float g_xn    [(size_t)BB * SEQ * DIM];
__device__ float g_qkv   [(size_t)BB * SEQ * 3 * DIM];
__device__ float g_qc    [(size_t)BB * SEQ * DIM];
__device__ float g_kv    [(size_t)BB * 2 * SEQ * 2 * DIM];
__device__ float g_memln [(size_t)BB * 2 * SEQ * DIM];
__device__ float g_scores[(size_t)BB * NH * SEQ * 2 * SEQ]; // 537 MB
__device__ float g_attn  [(size_t)BB * SEQ * DIM];
__device__ float g_tmp   [(size_t)BB * SEQ * DIM];
__device__ float g_x     [(size_t)BB * SEQ * DIM];
__device__ float g_mlp   [(size_t)BB * SEQ * 4 * DIM];

// ---------------------------------------------------------------------------
// Generic tiled GEMM.
//   TB=true : C[m,n] = alpha * sum_k A[m,k] * B[n,k]   (both K-contiguous)
//   TB=false: C[m,n] = alpha * sum_k A[m,k] * B[k,n]
// Batched via blockIdx.z with composite (outer, inner) strides:
//   ptr += (z / Hdiv) * SO + (z % Hdiv) * SI
// Requires: M % BM == 0, N % BN == 0, K % BK == 0 (guaranteed by launch choice),
// all leading dims multiples of 4, bases 16B aligned.
// ---------------------------------------------------------------------------
template <int BM, int BN, int BK, int TM, int TN, bool TB>
__global__ __launch_bounds__(256) void gemm_kernel(
    const float* __restrict__ A, int ldA, long long aSO, long long aSI,
    const float* __restrict__ B, int ldB, long long bSO, long long bSI,
    float*       __restrict__ C, int ldC, long long cSO, long long cSI,
    int K, int Hdiv, float alpha, const float* __restrict__ bias)
{
    const int z = blockIdx.z;
    A += (long long)(z / Hdiv) * aSO + (long long)(z % Hdiv) * aSI;
    B += (long long)(z / Hdiv) * bSO + (long long)(z % Hdiv) * bSI;
    C += (long long)(z / Hdiv) * cSO + (long long)(z % Hdiv) * cSI;

    __shared__ float As[BK][BM];
    __shared__ float Bs[BK][BN];

    const int tid = threadIdx.x;
    const int m0 = blockIdx.y * BM;
    const int n0 = blockIdx.x * BN;

    // Tile load indices (exactly one float4 per thread per operand:
    // BM*BK == BN*BK == 1024 for both instantiations).
    const int aRow = (tid * 4) / BK;
    const int aCol = (tid * 4) % BK;
    int bRow, bCol;
    if (TB) { bRow = (tid * 4) / BK; bCol = (tid * 4) % BK; }
    else    { bRow = (tid * 4) / BN; bCol = (tid * 4) % BN; }

    constexpr int TX = BN / TN;
    const int tx = tid % TX;
    const int ty = tid / TX;

    float acc[TM][TN];
#pragma unroll
    for (int i = 0; i < TM; i++)
#pragma unroll
        for (int j = 0; j < TN; j++) acc[i][j] = 0.f;

    for (int k0 = 0; k0 < K; k0 += BK) {
        float4 av = *(const float4*)(A + (long long)(m0 + aRow) * ldA + k0 + aCol);
        As[aCol + 0][aRow] = av.x;
        As[aCol + 1][aRow] = av.y;
        As[aCol + 2][aRow] = av.z;
        As[aCol + 3][aRow] = av.w;
        if (TB) {
            float4 bv = *(const float4*)(B + (long long)(n0 + bRow) * ldB + k0 + bCol);
            Bs[bCol + 0][bRow] = bv.x;
            Bs[bCol + 1][bRow] = bv.y;
            Bs[bCol + 2][bRow] = bv.z;
            Bs[bCol + 3][bRow] = bv.w;
        } else {
            float4 bv = *(const float4*)(B + (long long)(k0 + bRow) * ldB + n0 + bCol);
            *(float4*)&Bs[bRow][bCol] = bv;
        }
        __syncthreads();

#pragma unroll
        for (int k = 0; k < BK; k++) {
            float a[TM], b[TN];
#pragma unroll
            for (int i = 0; i < TM; i++) a[i] = As[k][ty * TM + i];
#pragma unroll
            for (int j = 0; j < TN; j++) b[j] = Bs[k][tx * TN + j];
#pragma unroll
            for (int i = 0; i < TM; i++)
#pragma unroll
                for (int j = 0; j < TN; j++) acc[i][j] += a[i] * b[j];
        }
        __syncthreads();
    }

#pragma unroll
    for (int i = 0; i < TM; i++) {
        const int m = m0 + ty * TM + i;
        float* cp = C + (long long)m * ldC + n0 + tx * TN;
#pragma unroll
        for (int j = 0; j < TN; j++) {
            float v = alpha * acc[i][j];
            if (bias) v += bias[n0 + tx * TN + j];
            cp[j] = v;
        }
    }
}

// ---------------------------------------------------------------------------
// LayerNorm (+ optional adaLN modulate). One block per row of D=1024.
// out = ln(x)*w * (1 + ada[scale]) + ada[shift]    (ada == null -> plain LN*w)
// ---------------------------------------------------------------------------
__global__ __launch_bounds__(256) void ln_mod_kernel(
    const float* __restrict__ x, long long xBS, int rowsPerBatch,
    const float* __restrict__ w,
    const float* __restrict__ ada, int chShift, int chScale,
    float* __restrict__ out, long long oBS, long long oOff)
{
    const int row = blockIdx.x;
    const int b = row / rowsPerBatch;
    const int r = row % rowsPerBatch;
    const float* xp = x + (long long)b * xBS + (long long)r * DIM;
    float* op = out + (long long)b * oBS + oOff + (long long)r * DIM;

    const int tid = threadIdx.x;
    float v[4];
    float s = 0.f, s2 = 0.f;
#pragma unroll
    for (int u = 0; u < 4; u++) {
        v[u] = xp[tid + u * 256];
        s += v[u];
        s2 += v[u] * v[u];
    }
    // block reduce (8 warps)
    __shared__ float shs[8], shs2[8];
#pragma unroll
    for (int o = 16; o > 0; o >>= 1) {
        s  += __shfl_down_sync(0xffffffffu, s,  o);
        s2 += __shfl_down_sync(0xffffffffu, s2, o);
    }
    if ((tid & 31) == 0) { shs[tid >> 5] = s; shs2[tid >> 5] = s2; }
    __syncthreads();
    __shared__ float meanSh, rstdSh;
    if (tid == 0) {
        float ts = 0.f, ts2 = 0.f;
#pragma unroll
        for (int i = 0; i < 8; i++) { ts += shs[i]; ts2 += shs2[i]; }
        float m = ts * (1.f / DIM);
        float var = ts2 * (1.f / DIM) - m * m;
        meanSh = m;
        rstdSh = rsqrtf(var + 1e-5f);
    }
    __syncthreads();
    const float m = meanSh, rs = rstdSh;

    const float* ap = nullptr;
    if (ada) ap = ada + ((long long)(b * SEQ + r) * ADA_CH) * DIM;

#pragma unroll
    for (int u = 0; u < 4; u++) {
        int d = tid + u * 256;
        float xn = (v[u] - m) * rs * w[d];
        if (ap) xn = xn * (1.f + ap[(long long)chScale * DIM + d]) + ap[(long long)chShift * DIM + d];
        op[d] = xn;
    }
}

// ---------------------------------------------------------------------------
// RoPE, in-place on a (tokens, NH, HDIM) view with token stride `tokStride`.
// pos = (token % tokensPerBatch) % SEQ.
// ---------------------------------------------------------------------------
__global__ void rope_kernel(float* __restrict__ x, long long tokStride,
                            int tokensPerBatch, int totalTokens,
                            const float* __restrict__ cosp,
                            const float* __restrict__ sinp)
{
    int idx = blockIdx.x * blockDim.x + threadIdx.x;
    int total = totalTokens * NH * (HDIM / 2);
    if (idx >= total) return;
    int d   = idx & 31;
    int h   = (idx >> 5) & (NH - 1);
    int tok = idx >> 9;
    int pos = (tok % tokensPerBatch) % SEQ;

    float* p = x + (long long)tok * tokStride + h * HDIM;
    float c = cosp[pos * HDIM + d];
    float s = sinp[pos * HDIM + d];
    float x1 = p[d], x2 = p[d + 32];
    p[d]      = x1 * c - x2 * s;
    p[d + 32] = x2 * c + x1 * s;
}

// ---------------------------------------------------------------------------
// Masked softmax: scores[(bh, q), :L] += mask[(b, q), :L]; softmax over L.
// blockIdx.x = q, blockIdx.y = bh.
// ---------------------------------------------------------------------------
template <int L>
__global__ __launch_bounds__(256) void softmax_kernel(
    float* __restrict__ s, const float* __restrict__ mask)
{
    const int q = blockIdx.x;
    const int bh = blockIdx.y;
    const int b = bh / NH;
    float* row = s + ((long long)bh * SEQ + q) * L;
    const float* mrow = mask + ((long long)b * SEQ + q) * L;

    constexpr int E = L / 256;
    const int tid = threadIdx.x;
    float v[E];
    float mx = -1e30f;
#pragma unroll
    for (int e = 0; e < E; e++) {
        v[e] = row[tid + e * 256] + mrow[tid + e * 256];
        mx = fmaxf(mx, v[e]);
    }
    __shared__ float sh[8];
#pragma unroll
    for (int o = 16; o > 0; o >>= 1) mx = fmaxf(mx, __shfl_down_sync(0xffffffffu, mx, o));
    if ((tid & 31) == 0) sh[tid >> 5] = mx;
    __syncthreads();
    __shared__ float bval;
    if (tid == 0) {
        float t = sh[0];
#pragma unroll
        for (int i = 1; i < 8; i++) t = fmaxf(t, sh[i]);
        bval = t;
    }
    __syncthreads();
    const float rmax = bval;

    float sum = 0.f;
#pragma unroll
    for (int e = 0; e < E; e++) {
        v[e] = __expf(v[e] - rmax);
        sum += v[e];
    }
    __syncthreads();
#pragma unroll
    for (int o = 16; o > 0; o >>= 1) sum += __shfl_down_sync(0xffffffffu, sum, o);
    if ((tid & 31) == 0) sh[tid >> 5] = sum;
    __syncthreads();
    if (tid == 0) {
        float t = 0.f;
#pragma unroll
        for (int i = 0; i < 8; i++) t += sh[i];
        bval = 1.f / t;
    }
    __syncthreads();
    const float inv = bval;
#pragma unroll
    for (int e = 0; e < E; e++) row[tid + e * 256] = v[e] * inv;
}

// ---------------------------------------------------------------------------
// out = xr + ada[chunk] * y   (elementwise over B*SEQ*DIM)
// ---------------------------------------------------------------------------
__global__ void resgate_kernel(const float* __restrict__ xr,
                               const float* __restrict__ y,
                               const float* __restrict__ ada, int ch,
                               float* __restrict__ out)
{
    long long i = (long long)blockIdx.x * 256 + threadIdx.x;
    long long t = i >> 10;       // token (DIM = 1024)
    int d = (int)(i & 1023);
    float g = ada[(t * ADA_CH + ch) * DIM + d];
    out[i] = xr[i] + g * y[i];
}

// gelu(tanh approx), in-place
__global__ void gelu_kernel(float* __restrict__ h, long long n)
{
    long long i = (long long)blockIdx.x * 256 + threadIdx.x;
    if (i >= n) return;
    float x = h[i];
    float t = tanhf(0.7978845608028654f * (x + 0.044715f * x * x * x));
    h[i] = 0.5f * x * (1.f + t);
}

// ---------------------------------------------------------------------------
// Host orchestration
// ---------------------------------------------------------------------------
static void gemm_big_tn(const float* A, int ldA,
                        const float* B, int ldB,
                        float* C, int ldC,
                        int M, int Nn, int K,
                        float alpha, const float* bias)
{
    dim3 g(Nn / 128, M / 128, 1);
    gemm_kernel<128, 128, 8, 8, 8, true><<<g, 256>>>(
        A, ldA, 0, 0, B, ldB, 0, 0, C, ldC, 0, 0, K, 1, alpha, bias);
}

extern "C" void kernel_launch(void* const* d_in, const int* in_sizes, int n_in,
                              void* d_out, int out_size)
{
    const float* q_x        = (const float*)d_in[0];
    const float* h_content  = (const float*)d_in[1];
    const float* h_obs      = (const float*)d_in[2];
    const float* t_cond     = (const float*)d_in[3];
    const float* cosp       = (const float*)d_in[4];
    const float* sinp       = (const float*)d_in[5];
    const float* M_QQ       = (const float*)d_in[6];
    const float* M_hyb      = (const float*)d_in[7];
    const float* w_ln_self  = (const float*)d_in[8];
    const float* w_qkv      = (const float*)d_in[9];
    const float* w_self_out = (const float*)d_in[10];
    const float* w_ln_cross = (const float*)d_in[11];
    const float* w_ln_mem   = (const float*)d_in[12];
    const float* w_qproj    = (const float*)d_in[13];
    const float* w_kvproj   = (const float*)d_in[14];
    const float* w_cross_out= (const float*)d_in[15];
    const float* w_ln_mlp   = (const float*)d_in[16];
    const float* w_mlp1     = (const float*)d_in[17];
    const float* b_mlp1     = (const float*)d_in[18];
    const float* w_mlp2     = (const float*)d_in[19];
    const float* b_mlp2     = (const float*)d_in[20];
    const float* w_ada      = (const float*)d_in[21];
    const float* b_ada      = (const float*)d_in[22];
    float* outp = (float*)d_out;

    float *ada, *xn, *qkv, *qc, *kv, *memln, *scores, *attn, *tmp, *x, *mlp;
    cudaGetSymbolAddress((void**)&ada,    g_ada);
    cudaGetSymbolAddress((void**)&xn,     g_xn);
    cudaGetSymbolAddress((void**)&qkv,    g_qkv);
    cudaGetSymbolAddress((void**)&qc,     g_qc);
    cudaGetSymbolAddress((void**)&kv,     g_kv);
    cudaGetSymbolAddress((void**)&memln,  g_memln);
    cudaGetSymbolAddress((void**)&scores, g_scores);
    cudaGetSymbolAddress((void**)&attn,   g_attn);
    cudaGetSymbolAddress((void**)&tmp,    g_tmp);
    cudaGetSymbolAddress((void**)&x,      g_x);
    cudaGetSymbolAddress((void**)&mlp,    g_mlp);

    const long long TOT = (long long)BB * SEQ * DIM;     // 4M
    const int ropeBlk = (BB * SEQ * NH * 32 + 255) / 256;
    const int ropeBlk2 = (BB * 2 * SEQ * NH * 32 + 255) / 256;

    // 1. adaLN projection (only the 9 used chunks): ada = t_cond @ w_ada[:9216].T + b_ada[:9216]
    gemm_big_tn(t_cond, CONDD, w_ada, CONDD, ada, ADA_N, BB * SEQ, ADA_N, CONDD, 1.f, b_ada);

    // ===================== Self-attention =====================
    // 2. xn = modulate(ln(q_x, w_ln_self), sh_s(0), sc_s(1))
    ln_mod_kernel<<<BB * SEQ, 256>>>(q_x, (long long)SEQ * DIM, SEQ, w_ln_self,
                                     ada, 0, 1, xn, (long long)SEQ * DIM, 0);
    // 3. qkv = xn @ w_qkv.T
    gemm_big_tn(xn, DIM, w_qkv, DIM, qkv, 3 * DIM, BB * SEQ, 3 * DIM, DIM, 1.f, nullptr);
    // 4. RoPE(q), RoPE(k)
    rope_kernel<<<ropeBlk, 256>>>(qkv,        3 * DIM, SEQ, BB * SEQ, cosp, sinp);
    rope_kernel<<<ropeBlk, 256>>>(qkv + DIM,  3 * DIM, SEQ, BB * SEQ, cosp, sinp);
    // 5. scores = (1/8) Q @ K^T   (batched over B*H)
    gemm_kernel<128, 128, 8, 8, 8, true><<<dim3(SEQ / 128, SEQ / 128, BB * NH), 256>>>(
        qkv,       3 * DIM, (long long)SEQ * 3 * DIM, HDIM,
        qkv + DIM, 3 * DIM, (long long)SEQ * 3 * DIM, HDIM,
        scores,    SEQ,     (long long)NH * SEQ * SEQ, (long long)SEQ * SEQ,
        HDIM, NH, 0.125f, nullptr);
    // 6. softmax(+M_QQ)
    softmax_kernel<1024><<<dim3(SEQ, BB * NH), 256>>>(scores, M_QQ);
    // 7. attn = P @ V
    gemm_kernel<64, 64, 16, 4, 4, false><<<dim3(1, SEQ / 64, BB * NH), 256>>>(
        scores,        SEQ,     (long long)NH * SEQ * SEQ, (long long)SEQ * SEQ,
        qkv + 2 * DIM, 3 * DIM, (long long)SEQ * 3 * DIM, HDIM,
        attn,          DIM,     (long long)SEQ * DIM, HDIM,
        SEQ, NH, 1.f, nullptr);
    // 8. tmp = attn @ w_self_out.T
    gemm_big_tn(attn, DIM, w_self_out, DIM, tmp, DIM, BB * SEQ, DIM, DIM, 1.f, nullptr);
    // 9. x = q_x + g_s(2) * tmp
    resgate_kernel<<<(int)(TOT / 256), 256>>>(q_x, tmp, ada, 2, x);

    // ===================== Cross-attention =====================
    // 10. xn = modulate(ln(x, w_ln_cross), sh_c(3), sc_c(4))
    ln_mod_kernel<<<BB * SEQ, 256>>>(x, (long long)SEQ * DIM, SEQ, w_ln_cross,
                                     ada, 3, 4, xn, (long long)SEQ * DIM, 0);
    // 11. qc = xn @ w_qproj.T ; 12. RoPE(qc)
    gemm_big_tn(xn, DIM, w_qproj, DIM, qc, DIM, BB * SEQ, DIM, DIM, 1.f, nullptr);
    rope_kernel<<<ropeBlk, 256>>>(qc, DIM, SEQ, BB * SEQ, cosp, sinp);
    // 13. memln = ln(concat(h_content, h_obs), w_ln_mem)
    ln_mod_kernel<<<BB * SEQ, 256>>>(h_content, (long long)SEQ * DIM, SEQ, w_ln_mem,
                                     nullptr, 0, 0, memln, (long long)2 * SEQ * DIM, 0);
    ln_mod_kernel<<<BB * SEQ, 256>>>(h_obs, (long long)SEQ * DIM, SEQ, w_ln_mem,
                                     nullptr, 0, 0, memln, (long long)2 * SEQ * DIM,
                                     (long long)SEQ * DIM);
    // 14. kv = memln @ w_kvproj.T
    gemm_big_tn(memln, DIM, w_kvproj, DIM, kv, 2 * DIM, BB * 2 * SEQ, 2 * DIM, DIM, 1.f, nullptr);
    // 15. RoPE(kc), positions (t % 2N) % N
    rope_kernel<<<ropeBlk2, 256>>>(kv, 2 * DIM, 2 * SEQ, BB * 2 * SEQ, cosp, sinp);
    // 16. scores = (1/8) qc @ kc^T  (N x 2N, batched B*H)
    gemm_kernel<128, 128, 8, 8, 8, true><<<dim3(2 * SEQ / 128, SEQ / 128, BB * NH), 256>>>(
        qc, DIM, (long long)SEQ * DIM, HDIM,
        kv, 2 * DIM, (long long)2 * SEQ * 2 * DIM, HDIM,
        scores, 2 * SEQ, (long long)NH * SEQ * 2 * SEQ, (long long)SEQ * 2 * SEQ,
        HDIM, NH, 0.125f, nullptr);
    // 17. softmax(+M_hyb)
    softmax_kernel<2048><<<dim3(SEQ, BB * NH), 256>>>(scores, M_hyb);
    // 18. attn = P @ Vc
    gemm_kernel<64, 64, 16, 4, 4, false><<<dim3(1, SEQ / 64, BB * NH), 256>>>(
        scores,   2 * SEQ, (long long)NH * SEQ * 2 * SEQ, (long long)SEQ * 2 * SEQ,
        kv + DIM, 2 * DIM, (long long)2 * SEQ * 2 * DIM, HDIM,
        attn,     DIM,     (long long)SEQ * DIM, HDIM,
        2 * SEQ, NH, 1.f, nullptr);
    // 19. tmp = attn @ w_cross_out.T ; 20. x += g_c(5) * tmp
    gemm_big_tn(attn, DIM, w_cross_out, DIM, tmp, DIM, BB * SEQ, DIM, DIM, 1.f, nullptr);
    resgate_kernel<<<(int)(TOT / 256), 256>>>(x, tmp, ada, 5, x);

    // ===================== MLP =====================
    // 21. xn = modulate(ln(x, w_ln_mlp), sh_m(6), sc_m(7))
    ln_mod_kernel<<<BB * SEQ, 256>>>(x, (long long)SEQ * DIM, SEQ, w_ln_mlp,
                                     ada, 6, 7, xn, (long long)SEQ * DIM, 0);
    // 22. mlp = xn @ w_mlp1.T + b_mlp1 ; 23. gelu
    gemm_big_tn(xn, DIM, w_mlp1, DIM, mlp, 4 * DIM, BB * SEQ, 4 * DIM, DIM, 1.f, b_mlp1);
    {
        long long n = (long long)BB * SEQ * 4 * DIM;
        gelu_kernel<<<(int)((n + 255) / 256), 256>>>(mlp, n);
    }
    // 24. tmp = mlp @ w_mlp2.T + b_mlp2 ; 25. out = x + g_m(8) * tmp
    gemm_big_tn(mlp, 4 * DIM, w_mlp2, 4 * DIM, tmp, DIM, BB * SEQ, DIM, 4 * DIM, 1.f, b_mlp2);
    resgate_kernel<<<(int)(TOT / 256), 256>>>(x, tmp, ada, 8, outp);
}

// round 9
// speedup vs baseline: 1.5573x; 1.5573x over previous
#include <cuda_runtime.h>
#include <mma.h>
#include <math.h>

using namespace nvcuda;

// Problem constants
#define BB    4
#define SEQ   1024
#define DIM   1024
#define NH    16
#define HDIM  64
#define CONDD 256
#define ADA_CH 9
#define ADA_N  (ADA_CH * DIM)   // 9216 (only the 9 used chunks of 12)

// ---------------------------------------------------------------------------
// Scratch (static device globals; no allocation allowed)
// ---------------------------------------------------------------------------
__device__ float g_ada   [(size_t)BB * SEQ * ADA_N];
__device__ float g_xn    [(size_t)BB * SEQ * DIM];
__device__ float g_qkv   [(size_t)BB * SEQ * 3 * DIM];
__device__ float g_qc    [(size_t)BB * SEQ * DIM];
__device__ float g_kv    [(size_t)BB * 2 * SEQ * 2 * DIM];
__device__ float g_memln [(size_t)BB * 2 * SEQ * DIM];
__device__ float g_scores[(size_t)BB * NH * SEQ * 2 * SEQ];
__device__ float g_attn  [(size_t)BB * SEQ * DIM];
__device__ float g_tmp   [(size_t)BB * SEQ * DIM];
__device__ float g_x     [(size_t)BB * SEQ * DIM];
__device__ float g_mlp   [(size_t)BB * SEQ * 4 * DIM];

// B-fragment layout selector: TN (B row-major [N,K], use as col_major K x N)
// vs NN (B row-major [K,N], row_major).
template <bool TB> struct BFrag {
    using type = wmma::fragment<wmma::matrix_b, 16, 16, 8, wmma::precision::tf32, wmma::col_major>;
};
template <> struct BFrag<false> {
    using type = wmma::fragment<wmma::matrix_b, 16, 16, 8, wmma::precision::tf32, wmma::row_major>;
};

// ---------------------------------------------------------------------------
// tf32 tensor-core GEMM (wmma m16n16k8, fp32 accumulate).
//   TB=true : C = alpha * A[M,K] * B[N,K]^T
//   TB=false: C = alpha * A[M,K] * B[K,N]
// Batched via blockIdx.z: ptr += (z/Hdiv)*SO + (z%Hdiv)*SI.
// Requires M%BM==0, N%BN==0, K%BK==0; leading dims multiple of 4 floats;
// bases 16B aligned. 256 threads (8 warps); warp grid (BM/WM) x (BN/WN).
// ---------------------------------------------------------------------------
template <int BM, int BN, int BK, int WM, int WN, bool TB>
__global__ __launch_bounds__(256) void wgemm_kernel(
    const float* __restrict__ A, int ldA, long long aSO, long long aSI,
    const float* __restrict__ B, int ldB, long long bSO, long long bSI,
    float*       __restrict__ C, int ldC, long long cSO, long long cSI,
    int K, int Hdiv, float alpha)
{
    const int z = blockIdx.z;
    A += (long long)(z / Hdiv) * aSO + (long long)(z % Hdiv) * aSI;
    B += (long long)(z / Hdiv) * bSO + (long long)(z % Hdiv) * bSI;
    C += (long long)(z / Hdiv) * cSO + (long long)(z % Hdiv) * cSI;

    constexpr int WARPS_N = BN / WN;
    constexpr int FM = WM / 16;
    constexpr int FN = WN / 16;
    constexpr int LDAS = BK + 4;
    constexpr int BR   = TB ? BN : BK;
    constexpr int LDBS = TB ? (BK + 4) : (BN + 4);

    __shared__ float As[BM][LDAS];
    __shared__ float Bs[BR][LDBS];

    const int tid = threadIdx.x;
    const int wid = tid >> 5;
    const int wm  = wid / WARPS_N;
    const int wn  = wid % WARPS_N;
    const int m0  = blockIdx.y * BM;
    const int n0  = blockIdx.x * BN;

    wmma::fragment<wmma::accumulator, 16, 16, 8, float> acc[FM][FN];
#pragma unroll
    for (int i = 0; i < FM; i++)
#pragma unroll
        for (int j = 0; j < FN; j++) wmma::fill_fragment(acc[i][j], 0.0f);

    for (int k0 = 0; k0 < K; k0 += BK) {
        // Load + convert A tile (BM x BK)
#pragma unroll
        for (int i = tid; i < BM * (BK / 4); i += 256) {
            int r = i / (BK / 4);
            int c = (i % (BK / 4)) * 4;
            float4 v = *(const float4*)(A + (long long)(m0 + r) * ldA + k0 + c);
            As[r][c + 0] = wmma::__float_to_tf32(v.x);
            As[r][c + 1] = wmma::__float_to_tf32(v.y);
            As[r][c + 2] = wmma::__float_to_tf32(v.z);
            As[r][c + 3] = wmma::__float_to_tf32(v.w);
        }
        // Load + convert B tile
        if (TB) {
#pragma unroll
            for (int i = tid; i < BN * (BK / 4); i += 256) {
                int r = i / (BK / 4);
                int c = (i % (BK / 4)) * 4;
                float4 v = *(const float4*)(B + (long long)(n0 + r) * ldB + k0 + c);
                Bs[r][c + 0] = wmma::__float_to_tf32(v.x);
                Bs[r][c + 1] = wmma::__float_to_tf32(v.y);
                Bs[r][c + 2] = wmma::__float_to_tf32(v.z);
                Bs[r][c + 3] = wmma::__float_to_tf32(v.w);
            }
        } else {
#pragma unroll
            for (int i = tid; i < BK * (BN / 4); i += 256) {
                int r = i / (BN / 4);
                int c = (i % (BN / 4)) * 4;
                float4 v = *(const float4*)(B + (long long)(k0 + r) * ldB + n0 + c);
                Bs[r][c + 0] = wmma::__float_to_tf32(v.x);
                Bs[r][c + 1] = wmma::__float_to_tf32(v.y);
                Bs[r][c + 2] = wmma::__float_to_tf32(v.z);
                Bs[r][c + 3] = wmma::__float_to_tf32(v.w);
            }
        }
        __syncthreads();

#pragma unroll
        for (int kk = 0; kk < BK; kk += 8) {
            wmma::fragment<wmma::matrix_a, 16, 16, 8, wmma::precision::tf32, wmma::row_major> af[FM];
            typename BFrag<TB>::type bf[FN];
#pragma unroll
            for (int i = 0; i < FM; i++)
                wmma::load_matrix_sync(af[i], &As[wm * WM + i * 16][kk], LDAS);
#pragma unroll
            for (int j = 0; j < FN; j++) {
                if (TB)
                    wmma::load_matrix_sync(bf[j], &Bs[wn * WN + j * 16][kk], LDBS);
                else
                    wmma::load_matrix_sync(bf[j], &Bs[kk][wn * WN + j * 16], LDBS);
            }
#pragma unroll
            for (int i = 0; i < FM; i++)
#pragma unroll
                for (int j = 0; j < FN; j++)
                    wmma::mma_sync(acc[i][j], af[i], bf[j], acc[i][j]);
        }
        __syncthreads();
    }

#pragma unroll
    for (int i = 0; i < FM; i++)
#pragma unroll
        for (int j = 0; j < FN; j++) {
            if (alpha != 1.0f) {
#pragma unroll
                for (int e = 0; e < acc[i][j].num_elements; e++) acc[i][j].x[e] *= alpha;
            }
            wmma::store_matrix_sync(
                C + (long long)(m0 + wm * WM + i * 16) * ldC + n0 + wn * WN + j * 16,
                acc[i][j], ldC, wmma::mem_row_major);
        }
}

// ---------------------------------------------------------------------------
// LayerNorm (+ optional adaLN modulate). One block per row of D=1024.
// ada-projection is computed WITHOUT bias; b_ada is added here (adab).
// ---------------------------------------------------------------------------
__global__ __launch_bounds__(256) void ln_mod_kernel(
    const float* __restrict__ x, long long xBS, int rowsPerBatch,
    const float* __restrict__ w,
    const float* __restrict__ ada, const float* __restrict__ adab,
    int chShift, int chScale,
    float* __restrict__ out, long long oBS, long long oOff)
{
    const int row = blockIdx.x;
    const int b = row / rowsPerBatch;
    const int r = row % rowsPerBatch;
    const float* xp = x + (long long)b * xBS + (long long)r * DIM;
    float* op = out + (long long)b * oBS + oOff + (long long)r * DIM;

    const int tid = threadIdx.x;
    float v[4];
    float s = 0.f, s2 = 0.f;
#pragma unroll
    for (int u = 0; u < 4; u++) {
        v[u] = xp[tid + u * 256];
        s += v[u];
        s2 += v[u] * v[u];
    }
    __shared__ float shs[8], shs2[8];
#pragma unroll
    for (int o = 16; o > 0; o >>= 1) {
        s  += __shfl_down_sync(0xffffffffu, s,  o);
        s2 += __shfl_down_sync(0xffffffffu, s2, o);
    }
    if ((tid & 31) == 0) { shs[tid >> 5] = s; shs2[tid >> 5] = s2; }
    __syncthreads();
    __shared__ float meanSh, rstdSh;
    if (tid == 0) {
        float ts = 0.f, ts2 = 0.f;
#pragma unroll
        for (int i = 0; i < 8; i++) { ts += shs[i]; ts2 += shs2[i]; }
        float m = ts * (1.f / DIM);
        float var = ts2 * (1.f / DIM) - m * m;
        meanSh = m;
        rstdSh = rsqrtf(var + 1e-5f);
    }
    __syncthreads();
    const float m = meanSh, rs = rstdSh;

    const float* ap = nullptr;
    if (ada) ap = ada + ((long long)(b * SEQ + r) * ADA_CH) * DIM;

#pragma unroll
    for (int u = 0; u < 4; u++) {
        int d = tid + u * 256;
        float xn = (v[u] - m) * rs * w[d];
        if (ap) {
            float sc = ap[(long long)chScale * DIM + d] + adab[chScale * DIM + d];
            float sh = ap[(long long)chShift * DIM + d] + adab[chShift * DIM + d];
            xn = xn * (1.f + sc) + sh;
        }
        op[d] = xn;
    }
}

// ---------------------------------------------------------------------------
// RoPE, in-place on a (tokens, NH, HDIM) view with token stride `tokStride`.
// ---------------------------------------------------------------------------
__global__ void rope_kernel(float* __restrict__ x, long long tokStride,
                            int tokensPerBatch, int totalTokens,
                            const float* __restrict__ cosp,
                            const float* __restrict__ sinp)
{
    int idx = blockIdx.x * blockDim.x + threadIdx.x;
    int total = totalTokens * NH * (HDIM / 2);
    if (idx >= total) return;
    int d   = idx & 31;
    int h   = (idx >> 5) & (NH - 1);
    int tok = idx >> 9;
    int pos = (tok % tokensPerBatch) % SEQ;

    float* p = x + (long long)tok * tokStride + h * HDIM;
    float c = cosp[pos * HDIM + d];
    float s = sinp[pos * HDIM + d];
    float x1 = p[d], x2 = p[d + 32];
    p[d]      = x1 * c - x2 * s;
    p[d + 32] = x2 * c + x1 * s;
}

// ---------------------------------------------------------------------------
// Masked softmax: scores[(bh, q), :L] += mask[(b, q), :L]; softmax over L.
// ---------------------------------------------------------------------------
template <int L>
__global__ __launch_bounds__(256) void softmax_kernel(
    float* __restrict__ s, const float* __restrict__ mask)
{
    const int q = blockIdx.x;
    const int bh = blockIdx.y;
    const int b = bh / NH;
    float* row = s + ((long long)bh * SEQ + q) * L;
    const float* mrow = mask + ((long long)b * SEQ + q) * L;

    constexpr int E = L / 256;
    const int tid = threadIdx.x;
    float v[E];
    float mx = -1e30f;
#pragma unroll
    for (int e = 0; e < E; e++) {
        v[e] = row[tid + e * 256] + mrow[tid + e * 256];
        mx = fmaxf(mx, v[e]);
    }
    __shared__ float sh[8];
#pragma unroll
    for (int o = 16; o > 0; o >>= 1) mx = fmaxf(mx, __shfl_down_sync(0xffffffffu, mx, o));
    if ((tid & 31) == 0) sh[tid >> 5] = mx;
    __syncthreads();
    __shared__ float bval;
    if (tid == 0) {
        float t = sh[0];
#pragma unroll
        for (int i = 1; i < 8; i++) t = fmaxf(t, sh[i]);
        bval = t;
    }
    __syncthreads();
    const float rmax = bval;

    float sum = 0.f;
#pragma unroll
    for (int e = 0; e < E; e++) {
        v[e] = __expf(v[e] - rmax);
        sum += v[e];
    }
    __syncthreads();
#pragma unroll
    for (int o = 16; o > 0; o >>= 1) sum += __shfl_down_sync(0xffffffffu, sum, o);
    if ((tid & 31) == 0) sh[tid >> 5] = sum;
    __syncthreads();
    if (tid == 0) {
        float t = 0.f;
#pragma unroll
        for (int i = 0; i < 8; i++) t += sh[i];
        bval = 1.f / t;
    }
    __syncthreads();
    const float inv = bval;
#pragma unroll
    for (int e = 0; e < E; e++) row[tid + e * 256] = v[e] * inv;
}

// ---------------------------------------------------------------------------
// out = xr + (ada[chunk]+b_ada[chunk]) * (y + ybias)   (ybias nullable)
// ---------------------------------------------------------------------------
__global__ void resgate_kernel(const float* __restrict__ xr,
                               const float* __restrict__ y,
                               const float* __restrict__ ybias,
                               const float* __restrict__ ada,
                               const float* __restrict__ adab, int ch,
                               float* __restrict__ out)
{
    long long i = (long long)blockIdx.x * 256 + threadIdx.x;
    long long t = i >> 10;       // token (DIM = 1024)
    int d = (int)(i & 1023);
    float g = ada[(t * ADA_CH + ch) * DIM + d] + adab[ch * DIM + d];
    float yv = y[i];
    if (ybias) yv += ybias[d];
    out[i] = xr[i] + g * yv;
}

// gelu(tanh approx) with bias add, in-place: h = gelu(h + bias[i % bmod])
__global__ void gelu_kernel(float* __restrict__ h, const float* __restrict__ bias,
                            long long n, int bmod)
{
    long long i = (long long)blockIdx.x * 256 + threadIdx.x;
    if (i >= n) return;
    float x = h[i] + bias[(int)(i % bmod)];
    float t = tanhf(0.7978845608028654f * (x + 0.044715f * x * x * x));
    h[i] = 0.5f * x * (1.f + t);
}

// ---------------------------------------------------------------------------
// Host orchestration
// ---------------------------------------------------------------------------
static void gemm_big_tn(const float* A, int ldA,
                        const float* B, int ldB,
                        float* C, int ldC,
                        int M, int Nn, int K)
{
    dim3 g(Nn / 128, M / 128, 1);
    wgemm_kernel<128, 128, 32, 64, 32, true><<<g, 256>>>(
        A, ldA, 0, 0, B, ldB, 0, 0, C, ldC, 0, 0, K, 1, 1.0f);
}

extern "C" void kernel_launch(void* const* d_in, const int* in_sizes, int n_in,
                              void* d_out, int out_size)
{
    const float* q_x        = (const float*)d_in[0];
    const float* h_content  = (const float*)d_in[1];
    const float* h_obs      = (const float*)d_in[2];
    const float* t_cond     = (const float*)d_in[3];
    const float* cosp       = (const float*)d_in[4];
    const float* sinp       = (const float*)d_in[5];
    const float* M_QQ       = (const float*)d_in[6];
    const float* M_hyb      = (const float*)d_in[7];
    const float* w_ln_self  = (const float*)d_in[8];
    const float* w_qkv      = (const float*)d_in[9];
    const float* w_self_out = (const float*)d_in[10];
    const float* w_ln_cross = (const float*)d_in[11];
    const float* w_ln_mem   = (const float*)d_in[12];
    const float* w_qproj    = (const float*)d_in[13];
    const float* w_kvproj   = (const float*)d_in[14];
    const float* w_cross_out= (const float*)d_in[15];
    const float* w_ln_mlp   = (const float*)d_in[16];
    const float* w_mlp1     = (const float*)d_in[17];
    const float* b_mlp1     = (const float*)d_in[18];
    const float* w_mlp2     = (const float*)d_in[19];
    const float* b_mlp2     = (const float*)d_in[20];
    const float* w_ada      = (const float*)d_in[21];
    const float* b_ada      = (const float*)d_in[22];
    float* outp = (float*)d_out;

    float *ada, *xn, *qkv, *qc, *kv, *memln, *scores, *attn, *tmp, *x, *mlp;
    cudaGetSymbolAddress((void**)&ada,    g_ada);
    cudaGetSymbolAddress((void**)&xn,     g_xn);
    cudaGetSymbolAddress((void**)&qkv,    g_qkv);
    cudaGetSymbolAddress((void**)&qc,     g_qc);
    cudaGetSymbolAddress((void**)&kv,     g_kv);
    cudaGetSymbolAddress((void**)&memln,  g_memln);
    cudaGetSymbolAddress((void**)&scores, g_scores);
    cudaGetSymbolAddress((void**)&attn,   g_attn);
    cudaGetSymbolAddress((void**)&tmp,    g_tmp);
    cudaGetSymbolAddress((void**)&x,      g_x);
    cudaGetSymbolAddress((void**)&mlp,    g_mlp);

    const long long TOT = (long long)BB * SEQ * DIM;     // 4M
    const int ropeBlk  = (BB * SEQ * NH * 32 + 255) / 256;
    const int ropeBlk2 = (BB * 2 * SEQ * NH * 32 + 255) / 256;

    // 1. ada = t_cond @ w_ada[:9216].T      (bias b_ada folded into consumers)
    gemm_big_tn(t_cond, CONDD, w_ada, CONDD, ada, ADA_N, BB * SEQ, ADA_N, CONDD);

    // ===================== Self-attention =====================
    ln_mod_kernel<<<BB * SEQ, 256>>>(q_x, (long long)SEQ * DIM, SEQ, w_ln_self,
                                     ada, b_ada, 0, 1, xn, (long long)SEQ * DIM, 0);
    gemm_big_tn(xn, DIM, w_qkv, DIM, qkv, 3 * DIM, BB * SEQ, 3 * DIM, DIM);
    rope_kernel<<<ropeBlk, 256>>>(qkv,        3 * DIM, SEQ, BB * SEQ, cosp, sinp);
    rope_kernel<<<ropeBlk, 256>>>(qkv + DIM,  3 * DIM, SEQ, BB * SEQ, cosp, sinp);
    // scores = (1/8) Q @ K^T   (batched over B*H)
    wgemm_kernel<128, 128, 32, 64, 32, true><<<dim3(SEQ / 128, SEQ / 128, BB * NH), 256>>>(
        qkv,       3 * DIM, (long long)SEQ * 3 * DIM, HDIM,
        qkv + DIM, 3 * DIM, (long long)SEQ * 3 * DIM, HDIM,
        scores,    SEQ,     (long long)NH * SEQ * SEQ, (long long)SEQ * SEQ,
        HDIM, NH, 0.125f);
    softmax_kernel<1024><<<dim3(SEQ, BB * NH), 256>>>(scores, M_QQ);
    // attn = P @ V   (NN)
    wgemm_kernel<128, 64, 32, 64, 16, false><<<dim3(1, SEQ / 128, BB * NH), 256>>>(
        scores,        SEQ,     (long long)NH * SEQ * SEQ, (long long)SEQ * SEQ,
        qkv + 2 * DIM, 3 * DIM, (long long)SEQ * 3 * DIM, HDIM,
        attn,          DIM,     (long long)SEQ * DIM, HDIM,
        SEQ, NH, 1.0f);
    gemm_big_tn(attn, DIM, w_self_out, DIM, tmp, DIM, BB * SEQ, DIM, DIM);
    resgate_kernel<<<(int)(TOT / 256), 256>>>(q_x, tmp, nullptr, ada, b_ada, 2, x);

    // ===================== Cross-attention =====================
    ln_mod_kernel<<<BB * SEQ, 256>>>(x, (long long)SEQ * DIM, SEQ, w_ln_cross,
                                     ada, b_ada, 3, 4, xn, (long long)SEQ * DIM, 0);
    gemm_big_tn(xn, DIM, w_qproj, DIM, qc, DIM, BB * SEQ, DIM, DIM);
    rope_kernel<<<ropeBlk, 256>>>(qc, DIM, SEQ, BB * SEQ, cosp, sinp);
    ln_mod_kernel<<<BB * SEQ, 256>>>(h_content, (long long)SEQ * DIM, SEQ, w_ln_mem,
                                     nullptr, nullptr, 0, 0, memln, (long long)2 * SEQ * DIM, 0);
    ln_mod_kernel<<<BB * SEQ, 256>>>(h_obs, (long long)SEQ * DIM, SEQ, w_ln_mem,
                                     nullptr, nullptr, 0, 0, memln, (long long)2 * SEQ * DIM,
                                     (long long)SEQ * DIM);
    gemm_big_tn(memln, DIM, w_kvproj, DIM, kv, 2 * DIM, BB * 2 * SEQ, 2 * DIM, DIM);
    rope_kernel<<<ropeBlk2, 256>>>(kv, 2 * DIM, 2 * SEQ, BB * 2 * SEQ, cosp, sinp);
    // scores = (1/8) qc @ kc^T  (N x 2N, batched B*H)
    wgemm_kernel<128, 128, 32, 64, 32, true><<<dim3(2 * SEQ / 128, SEQ / 128, BB * NH), 256>>>(
        qc, DIM, (long long)SEQ * DIM, HDIM,
        kv, 2 * DIM, (long long)2 * SEQ * 2 * DIM, HDIM,
        scores, 2 * SEQ, (long long)NH * SEQ * 2 * SEQ, (long long)SEQ * 2 * SEQ,
        HDIM, NH, 0.125f);
    softmax_kernel<2048><<<dim3(SEQ, BB * NH), 256>>>(scores, M_hyb);
    wgemm_kernel<128, 64, 32, 64, 16, false><<<dim3(1, SEQ / 128, BB * NH), 256>>>(
        scores,   2 * SEQ, (long long)NH * SEQ * 2 * SEQ, (long long)SEQ * 2 * SEQ,
        kv + DIM, 2 * DIM, (long long)2 * SEQ * 2 * DIM, HDIM,
        attn,     DIM,     (long long)SEQ * DIM, HDIM,
        2 * SEQ, NH, 1.0f);
    gemm_big_tn(attn, DIM, w_cross_out, DIM, tmp, DIM, BB * SEQ, DIM, DIM);
    resgate_kernel<<<(int)(TOT / 256), 256>>>(x, tmp, nullptr, ada, b_ada, 5, x);

    // ===================== MLP =====================
    ln_mod_kernel<<<BB * SEQ, 256>>>(x, (long long)SEQ * DIM, SEQ, w_ln_mlp,
                                     ada, b_ada, 6, 7, xn, (long long)SEQ * DIM, 0);
    gemm_big_tn(xn, DIM, w_mlp1, DIM, mlp, 4 * DIM, BB * SEQ, 4 * DIM, DIM);
    {
        long long n = (long long)BB * SEQ * 4 * DIM;
        gelu_kernel<<<(int)((n + 255) / 256), 256>>>(mlp, b_mlp1, n, 4 * DIM);
    }
    gemm_big_tn(mlp, 4 * DIM, w_mlp2, 4 * DIM, tmp, DIM, BB * SEQ, DIM, 4 * DIM);
    resgate_kernel<<<(int)(TOT / 256), 256>>>(x, tmp, b_mlp2, ada, b_ada, 8, outp);
}

// round 11
// speedup vs baseline: 1.6498x; 1.0594x over previous
#include <cuda_runtime.h>
#include <cuda_pipeline.h>
#include <mma.h>
#include <math.h>

using namespace nvcuda;

// Problem constants
#define BB    4
#define SEQ   1024
#define DIM   1024
#define NH    16
#define HDIM  64
#define CONDD 256
#define ADA_CH 9
#define ADA_N  (ADA_CH * DIM)

// ---------------------------------------------------------------------------
// Scratch (static device globals; no allocation allowed)
// ---------------------------------------------------------------------------
__device__ float g_ada   [(size_t)BB * SEQ * ADA_N];
__device__ float g_xn    [(size_t)BB * SEQ * DIM];
__device__ float g_qkv   [(size_t)BB * SEQ * 3 * DIM];
__device__ float g_qc    [(size_t)BB * SEQ * DIM];
__device__ float g_kv    [(size_t)BB * 2 * SEQ * 2 * DIM];
__device__ float g_memln [(size_t)BB * 2 * SEQ * DIM];
__device__ float g_scores[(size_t)BB * NH * SEQ * 2 * SEQ];
__device__ float g_attn  [(size_t)BB * SEQ * DIM];
__device__ float g_tmp   [(size_t)BB * SEQ * DIM];
__device__ float g_x     [(size_t)BB * SEQ * DIM];
__device__ float g_mlp   [(size_t)BB * SEQ * 4 * DIM];

template <bool TB> struct BFrag {
    using type = wmma::fragment<wmma::matrix_b, 16, 16, 8, wmma::precision::tf32, wmma::col_major>;
};
template <> struct BFrag<false> {
    using type = wmma::fragment<wmma::matrix_b, 16, 16, 8, wmma::precision::tf32, wmma::row_major>;
};

// ---------------------------------------------------------------------------
// tf32 tensor-core GEMM, cp.async double-buffered.
//   TB=true : C = alpha * A[M,K] * B[N,K]^T      TB=false: C = alpha * A * B
// Batched via blockIdx.z: ptr += (z/Hdiv)*SO + (z%Hdiv)*SI.
// Dynamic smem: 2 buffers of (A: BM x (BK+4), B: BR x LDBS).
// Raw fp32 staged; HMMA truncates to tf32 internally.
// ---------------------------------------------------------------------------
template <int BM, int BN, int BK, int WM, int WN, bool TB>
__global__ __launch_bounds__(256) void wgemm_kernel(
    const float* __restrict__ A, int ldA, long long aSO, long long aSI,
    const float* __restrict__ B, int ldB, long long bSO, long long bSI,
    float*       __restrict__ C, int ldC, long long cSO, long long cSI,
    int K, int Hdiv, float alpha)
{
    const int z = blockIdx.z;
    A += (long long)(z / Hdiv) * aSO + (long long)(z % Hdiv) * aSI;
    B += (long long)(z / Hdiv) * bSO + (long long)(z % Hdiv) * bSI;
    C += (long long)(z / Hdiv) * cSO + (long long)(z % Hdiv) * cSI;

    constexpr int WARPS_N = BN / WN;
    constexpr int FM = WM / 16;
    constexpr int FN = WN / 16;
    constexpr int LDAS = BK + 4;
    constexpr int BR   = TB ? BN : BK;
    constexpr int LDBS = TB ? (BK + 4) : (BN + 4);
    constexpr int ASZ  = BM * LDAS;     // floats per A buffer
    constexpr int BSZ  = BR * LDBS;

    extern __shared__ float sm[];
    float* As = sm;                // [2][ASZ]
    float* Bs = sm + 2 * ASZ;      // [2][BSZ]

    const int tid = threadIdx.x;
    const int wid = tid >> 5;
    const int wm  = wid / WARPS_N;
    const int wn  = wid % WARPS_N;
    const int m0  = blockIdx.y * BM;
    const int n0  = blockIdx.x * BN;

    wmma::fragment<wmma::accumulator, 16, 16, 8, float> acc[FM][FN];
#pragma unroll
    for (int i = 0; i < FM; i++)
#pragma unroll
        for (int j = 0; j < FN; j++) wmma::fill_fragment(acc[i][j], 0.0f);

    auto loadTile = [&](int k0, int buf) {
        float* Ab = As + buf * ASZ;
        float* Bb = Bs + buf * BSZ;
#pragma unroll
        for (int i = tid; i < BM * (BK / 4); i += 256) {
            int r = i / (BK / 4);
            int c = (i % (BK / 4)) * 4;
            __pipeline_memcpy_async(Ab + r * LDAS + c,
                                    A + (long long)(m0 + r) * ldA + k0 + c, 16);
        }
        if (TB) {
#pragma unroll
            for (int i = tid; i < BN * (BK / 4); i += 256) {
                int r = i / (BK / 4);
                int c = (i % (BK / 4)) * 4;
                __pipeline_memcpy_async(Bb + r * LDBS + c,
                                        B + (long long)(n0 + r) * ldB + k0 + c, 16);
            }
        } else {
#pragma unroll
            for (int i = tid; i < BK * (BN / 4); i += 256) {
                int r = i / (BN / 4);
                int c = (i % (BN / 4)) * 4;
                __pipeline_memcpy_async(Bb + r * LDBS + c,
                                        B + (long long)(k0 + r) * ldB + n0 + c, 16);
            }
        }
    };

    const int T = K / BK;
    loadTile(0, 0);
    __pipeline_commit();

    for (int t = 0; t < T; t++) {
        if (t + 1 < T) {
            loadTile((t + 1) * BK, (t + 1) & 1);
            __pipeline_commit();
            __pipeline_wait_prior(1);
        } else {
            __pipeline_wait_prior(0);
        }
        __syncthreads();

        const float* Ab = As + (t & 1) * ASZ;
        const float* Bb = Bs + (t & 1) * BSZ;
#pragma unroll
        for (int kk = 0; kk < BK; kk += 8) {
            wmma::fragment<wmma::matrix_a, 16, 16, 8, wmma::precision::tf32, wmma::row_major> af[FM];
            typename BFrag<TB>::type bf[FN];
#pragma unroll
            for (int i = 0; i < FM; i++)
                wmma::load_matrix_sync(af[i], Ab + (wm * WM + i * 16) * LDAS + kk, LDAS);
#pragma unroll
            for (int j = 0; j < FN; j++) {
                if (TB)
                    wmma::load_matrix_sync(bf[j], Bb + (wn * WN + j * 16) * LDBS + kk, LDBS);
                else
                    wmma::load_matrix_sync(bf[j], Bb + kk * LDBS + wn * WN + j * 16, LDBS);
            }
#pragma unroll
            for (int i = 0; i < FM; i++)
#pragma unroll
                for (int j = 0; j < FN; j++)
                    wmma::mma_sync(acc[i][j], af[i], bf[j], acc[i][j]);
        }
        __syncthreads();
    }

#pragma unroll
    for (int i = 0; i < FM; i++)
#pragma unroll
        for (int j = 0; j < FN; j++) {
            if (alpha != 1.0f) {
#pragma unroll
                for (int e = 0; e < acc[i][j].num_elements; e++) acc[i][j].x[e] *= alpha;
            }
            wmma::store_matrix_sync(
                C + (long long)(m0 + wm * WM + i * 16) * ldC + n0 + wn * WN + j * 16,
                acc[i][j], ldC, wmma::mem_row_major);
        }
}

// Dynamic smem sizes for the two instantiations used
#define SMEM_TN ((2 * 128 * 36 + 2 * 128 * 36) * 4)   // 73728
#define SMEM_NN ((2 * 128 * 36 + 2 * 32 * 68) * 4)    // 54272

// ---------------------------------------------------------------------------
// LayerNorm (+ optional adaLN modulate); b_ada folded in here.
// ---------------------------------------------------------------------------
__global__ __launch_bounds__(256) void ln_mod_kernel(
    const float* __restrict__ x, long long xBS, int rowsPerBatch,
    const float* __restrict__ w,
    const float* __restrict__ ada, const float* __restrict__ adab,
    int chShift, int chScale,
    float* __restrict__ out, long long oBS, long long oOff)
{
    const int row = blockIdx.x;
    const int b = row / rowsPerBatch;
    const int r = row % rowsPerBatch;
    const float* xp = x + (long long)b * xBS + (long long)r * DIM;
    float* op = out + (long long)b * oBS + oOff + (long long)r * DIM;

    const int tid = threadIdx.x;
    float v[4];
    float s = 0.f, s2 = 0.f;
#pragma unroll
    for (int u = 0; u < 4; u++) {
        v[u] = xp[tid + u * 256];
        s += v[u];
        s2 += v[u] * v[u];
    }
    __shared__ float shs[8], shs2[8];
#pragma unroll
    for (int o = 16; o > 0; o >>= 1) {
        s  += __shfl_down_sync(0xffffffffu, s,  o);
        s2 += __shfl_down_sync(0xffffffffu, s2, o);
    }
    if ((tid & 31) == 0) { shs[tid >> 5] = s; shs2[tid >> 5] = s2; }
    __syncthreads();
    __shared__ float meanSh, rstdSh;
    if (tid == 0) {
        float ts = 0.f, ts2 = 0.f;
#pragma unroll
        for (int i = 0; i < 8; i++) { ts += shs[i]; ts2 += shs2[i]; }
        float m = ts * (1.f / DIM);
        float var = ts2 * (1.f / DIM) - m * m;
        meanSh = m;
        rstdSh = rsqrtf(var + 1e-5f);
    }
    __syncthreads();
    const float m = meanSh, rs = rstdSh;

    const float* ap = nullptr;
    if (ada) ap = ada + ((long long)(b * SEQ + r) * ADA_CH) * DIM;

#pragma unroll
    for (int u = 0; u < 4; u++) {
        int d = tid + u * 256;
        float xn = (v[u] - m) * rs * w[d];
        if (ap) {
            float sc = ap[(long long)chScale * DIM + d] + adab[chScale * DIM + d];
            float sh = ap[(long long)chShift * DIM + d] + adab[chShift * DIM + d];
            xn = xn * (1.f + sc) + sh;
        }
        op[d] = xn;
    }
}

// ---------------------------------------------------------------------------
// RoPE, in-place
// ---------------------------------------------------------------------------
__global__ void rope_kernel(float* __restrict__ x, long long tokStride,
                            int tokensPerBatch, int totalTokens,
                            const float* __restrict__ cosp,
                            const float* __restrict__ sinp)
{
    int idx = blockIdx.x * blockDim.x + threadIdx.x;
    int total = totalTokens * NH * (HDIM / 2);
    if (idx >= total) return;
    int d   = idx & 31;
    int h   = (idx >> 5) & (NH - 1);
    int tok = idx >> 9;
    int pos = (tok % tokensPerBatch) % SEQ;

    float* p = x + (long long)tok * tokStride + h * HDIM;
    float c = cosp[pos * HDIM + d];
    float s = sinp[pos * HDIM + d];
    float x1 = p[d], x2 = p[d + 32];
    p[d]      = x1 * c - x2 * s;
    p[d + 32] = x2 * c + x1 * s;
}

// ---------------------------------------------------------------------------
// Masked softmax
// ---------------------------------------------------------------------------
template <int L>
__global__ __launch_bounds__(256) void softmax_kernel(
    float* __restrict__ s, const float* __restrict__ mask)
{
    const int q = blockIdx.x;
    const int bh = blockIdx.y;
    const int b = bh / NH;
    float* row = s + ((long long)bh * SEQ + q) * L;
    const float* mrow = mask + ((long long)b * SEQ + q) * L;

    constexpr int E = L / 256;
    const int tid = threadIdx.x;
    float v[E];
    float mx = -1e30f;
#pragma unroll
    for (int e = 0; e < E; e++) {
        v[e] = row[tid + e * 256] + mrow[tid + e * 256];
        mx = fmaxf(mx, v[e]);
    }
    __shared__ float sh[8];
#pragma unroll
    for (int o = 16; o > 0; o >>= 1) mx = fmaxf(mx, __shfl_down_sync(0xffffffffu, mx, o));
    if ((tid & 31) == 0) sh[tid >> 5] = mx;
    __syncthreads();
    __shared__ float bval;
    if (tid == 0) {
        float t = sh[0];
#pragma unroll
        for (int i = 1; i < 8; i++) t = fmaxf(t, sh[i]);
        bval = t;
    }
    __syncthreads();
    const float rmax = bval;

    float sum = 0.f;
#pragma unroll
    for (int e = 0; e < E; e++) {
        v[e] = __expf(v[e] - rmax);
        sum += v[e];
    }
    __syncthreads();
#pragma unroll
    for (int o = 16; o > 0; o >>= 1) sum += __shfl_down_sync(0xffffffffu, sum, o);
    if ((tid & 31) == 0) sh[tid >> 5] = sum;
    __syncthreads();
    if (tid == 0) {
        float t = 0.f;
#pragma unroll
        for (int i = 0; i < 8; i++) t += sh[i];
        bval = 1.f / t;
    }
    __syncthreads();
    const float inv = bval;
#pragma unroll
    for (int e = 0; e < E; e++) row[tid + e * 256] = v[e] * inv;
}

// ---------------------------------------------------------------------------
// out = xr + (ada[chunk]+b_ada[chunk]) * (y + ybias)
// ---------------------------------------------------------------------------
__global__ void resgate_kernel(const float* __restrict__ xr,
                               const float* __restrict__ y,
                               const float* __restrict__ ybias,
                               const float* __restrict__ ada,
                               const float* __restrict__ adab, int ch,
                               float* __restrict__ out)
{
    long long i = (long long)blockIdx.x * 256 + threadIdx.x;
    long long t = i >> 10;
    int d = (int)(i & 1023);
    float g = ada[(t * ADA_CH + ch) * DIM + d] + adab[ch * DIM + d];
    float yv = y[i];
    if (ybias) yv += ybias[d];
    out[i] = xr[i] + g * yv;
}

// gelu(tanh approx) with bias
__global__ void gelu_kernel(float* __restrict__ h, const float* __restrict__ bias,
                            long long n, int bmod)
{
    long long i = (long long)blockIdx.x * 256 + threadIdx.x;
    if (i >= n) return;
    float x = h[i] + bias[(int)(i % bmod)];
    float t = tanhf(0.7978845608028654f * (x + 0.044715f * x * x * x));
    h[i] = 0.5f * x * (1.f + t);
}

// ---------------------------------------------------------------------------
// Host orchestration
// ---------------------------------------------------------------------------
static void gemm_big_tn(const float* A, int ldA,
                        const float* B, int ldB,
                        float* C, int ldC,
                        int M, int Nn, int K)
{
    dim3 g(Nn / 128, M / 128, 1);
    wgemm_kernel<128, 128, 32, 64, 32, true><<<g, 256, SMEM_TN>>>(
        A, ldA, 0, 0, B, ldB, 0, 0, C, ldC, 0, 0, K, 1, 1.0f);
}

extern "C" void kernel_launch(void* const* d_in, const int* in_sizes, int n_in,
                              void* d_out, int out_size)
{
    const float* q_x        = (const float*)d_in[0];
    const float* h_content  = (const float*)d_in[1];
    const float* h_obs      = (const float*)d_in[2];
    const float* t_cond     = (const float*)d_in[3];
    const float* cosp       = (const float*)d_in[4];
    const float* sinp       = (const float*)d_in[5];
    const float* M_QQ       = (const float*)d_in[6];
    const float* M_hyb      = (const float*)d_in[7];
    const float* w_ln_self  = (const float*)d_in[8];
    const float* w_qkv      = (const float*)d_in[9];
    const float* w_self_out = (const float*)d_in[10];
    const float* w_ln_cross = (const float*)d_in[11];
    const float* w_ln_mem   = (const float*)d_in[12];
    const float* w_qproj    = (const float*)d_in[13];
    const float* w_kvproj   = (const float*)d_in[14];
    const float* w_cross_out= (const float*)d_in[15];
    const float* w_ln_mlp   = (const float*)d_in[16];
    const float* w_mlp1     = (const float*)d_in[17];
    const float* b_mlp1     = (const float*)d_in[18];
    const float* w_mlp2     = (const float*)d_in[19];
    const float* b_mlp2     = (const float*)d_in[20];
    const float* w_ada      = (const float*)d_in[21];
    const float* b_ada      = (const float*)d_in[22];
    float* outp = (float*)d_out;

    // Opt-in smem above 48 KB for the two wgemm instantiations (idempotent, host-side)
    cudaFuncSetAttribute(wgemm_kernel<128, 128, 32, 64, 32, true>,
                         cudaFuncAttributeMaxDynamicSharedMemorySize, SMEM_TN);
    cudaFuncSetAttribute(wgemm_kernel<128, 64, 32, 64, 16, false>,
                         cudaFuncAttributeMaxDynamicSharedMemorySize, SMEM_NN);

    float *ada, *xn, *qkv, *qc, *kv, *memln, *scores, *attn, *tmp, *x, *mlp;
    cudaGetSymbolAddress((void**)&ada,    g_ada);
    cudaGetSymbolAddress((void**)&xn,     g_xn);
    cudaGetSymbolAddress((void**)&qkv,    g_qkv);
    cudaGetSymbolAddress((void**)&qc,     g_qc);
    cudaGetSymbolAddress((void**)&kv,     g_kv);
    cudaGetSymbolAddress((void**)&memln,  g_memln);
    cudaGetSymbolAddress((void**)&scores, g_scores);
    cudaGetSymbolAddress((void**)&attn,   g_attn);
    cudaGetSymbolAddress((void**)&tmp,    g_tmp);
    cudaGetSymbolAddress((void**)&x,      g_x);
    cudaGetSymbolAddress((void**)&mlp,    g_mlp);

    const long long TOT = (long long)BB * SEQ * DIM;
    const int ropeBlk  = (BB * SEQ * NH * 32 + 255) / 256;
    const int ropeBlk2 = (BB * 2 * SEQ * NH * 32 + 255) / 256;

    // 1. ada = t_cond @ w_ada[:9216].T  (b_ada folded into consumers)
    gemm_big_tn(t_cond, CONDD, w_ada, CONDD, ada, ADA_N, BB * SEQ, ADA_N, CONDD);

    // ===================== Self-attention =====================
    ln_mod_kernel<<<BB * SEQ, 256>>>(q_x, (long long)SEQ * DIM, SEQ, w_ln_self,
                                     ada, b_ada, 0, 1, xn, (long long)SEQ * DIM, 0);
    gemm_big_tn(xn, DIM, w_qkv, DIM, qkv, 3 * DIM, BB * SEQ, 3 * DIM, DIM);
    rope_kernel<<<ropeBlk, 256>>>(qkv,        3 * DIM, SEQ, BB * SEQ, cosp, sinp);
    rope_kernel<<<ropeBlk, 256>>>(qkv + DIM,  3 * DIM, SEQ, BB * SEQ, cosp, sinp);
    wgemm_kernel<128, 128, 32, 64, 32, true><<<dim3(SEQ / 128, SEQ / 128, BB * NH), 256, SMEM_TN>>>(
        qkv,       3 * DIM, (long long)SEQ * 3 * DIM, HDIM,
        qkv + DIM, 3 * DIM, (long long)SEQ * 3 * DIM, HDIM,
        scores,    SEQ,     (long long)NH * SEQ * SEQ, (long long)SEQ * SEQ,
        HDIM, NH, 0.125f);
    softmax_kernel<1024><<<dim3(SEQ, BB * NH), 256>>>(scores, M_QQ);
    wgemm_kernel<128, 64, 32, 64, 16, false><<<dim3(1, SEQ / 128, BB * NH), 256, SMEM_NN>>>(
        scores,        SEQ,     (long long)NH * SEQ * SEQ, (long long)SEQ * SEQ,
        qkv + 2 * DIM, 3 * DIM, (long long)SEQ * 3 * DIM, HDIM,
        attn,          DIM,     (long long)SEQ * DIM, HDIM,
        SEQ, NH, 1.0f);
    gemm_big_tn(attn, DIM, w_self_out, DIM, tmp, DIM, BB * SEQ, DIM, DIM);
    resgate_kernel<<<(int)(TOT / 256), 256>>>(q_x, tmp, nullptr, ada, b_ada, 2, x);

    // ===================== Cross-attention =====================
    ln_mod_kernel<<<BB * SEQ, 256>>>(x, (long long)SEQ * DIM, SEQ, w_ln_cross,
                                     ada, b_ada, 3, 4, xn, (long long)SEQ * DIM, 0);
    gemm_big_tn(xn, DIM, w_qproj, DIM, qc, DIM, BB * SEQ, DIM, DIM);
    rope_kernel<<<ropeBlk, 256>>>(qc, DIM, SEQ, BB * SEQ, cosp, sinp);
    ln_mod_kernel<<<BB * SEQ, 256>>>(h_content, (long long)SEQ * DIM, SEQ, w_ln_mem,
                                     nullptr, nullptr, 0, 0, memln, (long long)2 * SEQ * DIM, 0);
    ln_mod_kernel<<<BB * SEQ, 256>>>(h_obs, (long long)SEQ * DIM, SEQ, w_ln_mem,
                                     nullptr, nullptr, 0, 0, memln, (long long)2 * SEQ * DIM,
                                     (long long)SEQ * DIM);
    gemm_big_tn(memln, DIM, w_kvproj, DIM, kv, 2 * DIM, BB * 2 * SEQ, 2 * DIM, DIM);
    rope_kernel<<<ropeBlk2, 256>>>(kv, 2 * DIM, 2 * SEQ, BB * 2 * SEQ, cosp, sinp);
    wgemm_kernel<128, 128, 32, 64, 32, true><<<dim3(2 * SEQ / 128, SEQ / 128, BB * NH), 256, SMEM_TN>>>(
        qc, DIM, (long long)SEQ * DIM, HDIM,
        kv, 2 * DIM, (long long)2 * SEQ * 2 * DIM, HDIM,
        scores, 2 * SEQ, (long long)NH * SEQ * 2 * SEQ, (long long)SEQ * 2 * SEQ,
        HDIM, NH, 0.125f);
    softmax_kernel<2048><<<dim3(SEQ, BB * NH), 256>>>(scores, M_hyb);
    wgemm_kernel<128, 64, 32, 64, 16, false><<<dim3(1, SEQ / 128, BB * NH), 256, SMEM_NN>>>(
        scores,   2 * SEQ, (long long)NH * SEQ * 2 * SEQ, (long long)SEQ * 2 * SEQ,
        kv + DIM, 2 * DIM, (long long)2 * SEQ * 2 * DIM, HDIM,
        attn,     DIM,     (long long)SEQ * DIM, HDIM,
        2 * SEQ, NH, 1.0f);
    gemm_big_tn(attn, DIM, w_cross_out, DIM, tmp, DIM, BB * SEQ, DIM, DIM);
    resgate_kernel<<<(int)(TOT / 256), 256>>>(x, tmp, nullptr, ada, b_ada, 5, x);

    // ===================== MLP =====================
    ln_mod_kernel<<<BB * SEQ, 256>>>(x, (long long)SEQ * DIM, SEQ, w_ln_mlp,
                                     ada, b_ada, 6, 7, xn, (long long)SEQ * DIM, 0);
    gemm_big_tn(xn, DIM, w_mlp1, DIM, mlp, 4 * DIM, BB * SEQ, 4 * DIM, DIM);
    {
        long long n = (long long)BB * SEQ * 4 * DIM;
        gelu_kernel<<<(int)((n + 255) / 256), 256>>>(mlp, b_mlp1, n, 4 * DIM);
    }
    gemm_big_tn(mlp, 4 * DIM, w_mlp2, 4 * DIM, tmp, DIM, BB * SEQ, DIM, 4 * DIM);
    resgate_kernel<<<(int)(TOT / 256), 256>>>(x, tmp, b_mlp2, ada, b_ada, 8, outp);
}